// round 1
// baseline (speedup 1.0000x reference)
#include <cuda_runtime.h>
#include <cstddef>

#define HD 128
#define NMAX 100000
#define GMAX 1024

// ---------------- scratch (device globals; no allocation allowed) ----------
__device__ __align__(256) float g_buf0[NMAX * HD];   // h (layer output)
__device__ __align__(256) float g_buf1[NMAX * HD];   // m = h @ W
__device__ __align__(256) float g_buf2[NMAX * HD];   // aggregation target
__device__ __align__(256) float g_dinv[NMAX];        // deg -> rsqrt(deg)
__device__ __align__(256) float g_pooled[GMAX * HD];
__device__ __align__(256) float g_counts[GMAX];

// ---------------- degree ---------------------------------------------------
__global__ void deg_init(float* __restrict__ deg, int n) {
    int i = blockIdx.x * blockDim.x + threadIdx.x;
    if (i < n) deg[i] = 1.0f;   // self-loop
}

__global__ void deg_count(const int* __restrict__ dst, float* __restrict__ deg, int E) {
    int e = blockIdx.x * blockDim.x + threadIdx.x;
    if (e < E) atomicAdd(&deg[dst[e]], 1.0f);
}

__global__ void deg_rsqrt(float* __restrict__ deg, int n) {
    int i = blockIdx.x * blockDim.x + threadIdx.x;
    if (i < n) deg[i] = rsqrtf(deg[i]);
}

// ---------------- GEMM: C[n,128] = A[n,128] @ B[128,128] -------------------
// 128x128 tile per block, BK=32, 256 threads, 8x8 microtile per thread.
__global__ __launch_bounds__(256) void gemm_nn(
    const float* __restrict__ A, const float* __restrict__ B,
    float* __restrict__ C, int n)
{
    __shared__ float As[32][128];   // [k][m]
    __shared__ float Bs[32][128];   // [k][n]

    const int tid = threadIdx.x;
    const int tx  = tid & 15;       // 0..15 -> output cols tx*8..
    const int ty  = tid >> 4;       // 0..15 -> output rows ty*8..
    const int row0 = blockIdx.x * 128;

    float acc[8][8];
#pragma unroll
    for (int i = 0; i < 8; i++)
#pragma unroll
        for (int j = 0; j < 8; j++) acc[i][j] = 0.0f;

    for (int k0 = 0; k0 < 128; k0 += 32) {
        // load A tile (128 rows x 32 cols) transposed into As, B tile (32x128) into Bs
#pragma unroll
        for (int l = 0; l < 4; l++) {
            int idx = tid + l * 256;            // 0..1023 (float4 index)
            // A: 8 float4 per row
            int r = idx >> 3;
            int c = (idx & 7) << 2;
            int gr = row0 + r;
            float4 v = make_float4(0.f, 0.f, 0.f, 0.f);
            if (gr < n) v = *(const float4*)(A + (size_t)gr * HD + k0 + c);
            As[c + 0][r] = v.x; As[c + 1][r] = v.y;
            As[c + 2][r] = v.z; As[c + 3][r] = v.w;
            // B: 32 float4 per row
            int r2 = idx >> 5;                  // 0..31
            int c2 = (idx & 31) << 2;           // 0..124
            *(float4*)&Bs[r2][c2] = *(const float4*)(B + (size_t)(k0 + r2) * HD + c2);
        }
        __syncthreads();

#pragma unroll
        for (int k = 0; k < 32; k++) {
            float a[8], b[8];
            *(float4*)&a[0] = *(const float4*)&As[k][ty * 8];
            *(float4*)&a[4] = *(const float4*)&As[k][ty * 8 + 4];
            *(float4*)&b[0] = *(const float4*)&Bs[k][tx * 8];
            *(float4*)&b[4] = *(const float4*)&Bs[k][tx * 8 + 4];
#pragma unroll
            for (int i = 0; i < 8; i++)
#pragma unroll
                for (int j = 0; j < 8; j++)
                    acc[i][j] = fmaf(a[i], b[j], acc[i][j]);
        }
        __syncthreads();
    }

#pragma unroll
    for (int i = 0; i < 8; i++) {
        int gr = row0 + ty * 8 + i;
        if (gr < n) {
            float4 v0 = make_float4(acc[i][0], acc[i][1], acc[i][2], acc[i][3]);
            float4 v1 = make_float4(acc[i][4], acc[i][5], acc[i][6], acc[i][7]);
            *(float4*)(C + (size_t)gr * HD + tx * 8)     = v0;
            *(float4*)(C + (size_t)gr * HD + tx * 8 + 4) = v1;
        }
    }
}

// ---------------- agg init: agg[i] = m[i] * dinv[i]^2 + bias ---------------
__global__ void selfloop_bias(const float* __restrict__ m, const float* __restrict__ dinv,
                              const float* __restrict__ bias, float* __restrict__ agg, int n)
{
    int idx = blockIdx.x * blockDim.x + threadIdx.x;   // over n*32 float4s
    if (idx >= n * 32) return;
    int i  = idx >> 5;
    int c4 = (idx & 31) << 2;
    float w = dinv[i];
    w = w * w;
    float4 v  = *(const float4*)(m + (size_t)i * HD + c4);
    float4 bb = *(const float4*)(bias + c4);
    v.x = fmaf(v.x, w, bb.x);
    v.y = fmaf(v.y, w, bb.y);
    v.z = fmaf(v.z, w, bb.z);
    v.w = fmaf(v.w, w, bb.w);
    *(float4*)(agg + (size_t)i * HD + c4) = v;
}

// ---------------- edge scatter: agg[dst] += m[src] * dinv[src]*dinv[dst] ---
// one warp per edge; lane handles 4 channels via red.global.add.v4.f32
__global__ void scatter_edges(const float* __restrict__ m,
                              const int* __restrict__ src, const int* __restrict__ dst,
                              const float* __restrict__ dinv,
                              float* __restrict__ agg, int E)
{
    int e = blockIdx.x * (blockDim.x >> 5) + (threadIdx.x >> 5);
    if (e >= E) return;
    int lane = threadIdx.x & 31;
    int s = src[e];
    int d = dst[e];
    float nrm = dinv[s] * dinv[d];
    float4 v = *(const float4*)(m + (size_t)s * HD + (lane << 2));
    float* p = agg + (size_t)d * HD + (lane << 2);
    asm volatile("red.global.add.v4.f32 [%0], {%1, %2, %3, %4};"
                 :: "l"(p), "f"(v.x * nrm), "f"(v.y * nrm),
                    "f"(v.z * nrm), "f"(v.w * nrm)
                 : "memory");
}

// ---------------- relu ------------------------------------------------------
__global__ void relu_k(const float* __restrict__ in, float* __restrict__ out, int n4) {
    int idx = blockIdx.x * blockDim.x + threadIdx.x;
    if (idx >= n4) return;
    float4 v = *(const float4*)(in + (size_t)idx * 4);
    v.x = fmaxf(v.x, 0.f); v.y = fmaxf(v.y, 0.f);
    v.z = fmaxf(v.z, 0.f); v.w = fmaxf(v.w, 0.f);
    *(float4*)(out + (size_t)idx * 4) = v;
}

// ---------------- pooling ---------------------------------------------------
__global__ void zero_pool(float* __restrict__ pooled, float* __restrict__ counts, int G) {
    int i = blockIdx.x * blockDim.x + threadIdx.x;
    if (i < G * HD) pooled[i] = 0.0f;
    if (i < G) counts[i] = 0.0f;
}

__global__ void pool_nodes(const float* __restrict__ h, const int* __restrict__ batch,
                           float* __restrict__ pooled, float* __restrict__ counts, int n)
{
    int i = blockIdx.x * (blockDim.x >> 5) + (threadIdx.x >> 5);
    if (i >= n) return;
    int lane = threadIdx.x & 31;
    int g = batch[i];
    float4 v = *(const float4*)(h + (size_t)i * HD + (lane << 2));
    float* p = pooled + (size_t)g * HD + (lane << 2);
    asm volatile("red.global.add.v4.f32 [%0], {%1, %2, %3, %4};"
                 :: "l"(p), "f"(v.x), "f"(v.y), "f"(v.z), "f"(v.w)
                 : "memory");
    if (lane == 0) atomicAdd(&counts[g], 1.0f);
}

// ---------------- final linear head: out[g, 0:2] ---------------------------
__global__ void final_linear(const float* __restrict__ pooled, const float* __restrict__ counts,
                             const float* __restrict__ linW, const float* __restrict__ linb,
                             float* __restrict__ out)
{
    int g = blockIdx.x;
    int c = threadIdx.x;          // 128 threads
    float cnt = fmaxf(counts[g], 1.0f);
    float p = pooled[g * HD + c] / cnt;
    float v0 = p * linW[c * 2 + 0];
    float v1 = p * linW[c * 2 + 1];
#pragma unroll
    for (int o = 16; o > 0; o >>= 1) {
        v0 += __shfl_xor_sync(0xffffffffu, v0, o);
        v1 += __shfl_xor_sync(0xffffffffu, v1, o);
    }
    __shared__ float s0[4], s1[4];
    int w = threadIdx.x >> 5;
    if ((threadIdx.x & 31) == 0) { s0[w] = v0; s1[w] = v1; }
    __syncthreads();
    if (threadIdx.x == 0) {
        out[g * 2 + 0] = s0[0] + s0[1] + s0[2] + s0[3] + linb[0];
        out[g * 2 + 1] = s1[0] + s1[1] + s1[2] + s1[3] + linb[1];
    }
}

// ---------------- launch ----------------------------------------------------
extern "C" void kernel_launch(void* const* d_in, const int* in_sizes, int n_in,
                              void* d_out, int out_size)
{
    const float* x     = (const float*)d_in[0];
    const int*   ei    = (const int*)d_in[1];
    const int*   batch = (const int*)d_in[2];
    const float* W[4]  = {(const float*)d_in[3], (const float*)d_in[5],
                          (const float*)d_in[7], (const float*)d_in[9]};
    const float* bv[4] = {(const float*)d_in[4], (const float*)d_in[6],
                          (const float*)d_in[8], (const float*)d_in[10]};
    const float* linW  = (const float*)d_in[11];
    const float* linb  = (const float*)d_in[12];
    float* out = (float*)d_out;

    const int n = in_sizes[0] / HD;
    const int E = in_sizes[1] / 2;
    const int G = out_size / 2;
    const int* src = ei;
    const int* dst = ei + E;

    float *buf0, *buf1, *buf2, *dinv, *pooled, *counts;
    cudaGetSymbolAddress((void**)&buf0,   g_buf0);
    cudaGetSymbolAddress((void**)&buf1,   g_buf1);
    cudaGetSymbolAddress((void**)&buf2,   g_buf2);
    cudaGetSymbolAddress((void**)&dinv,   g_dinv);
    cudaGetSymbolAddress((void**)&pooled, g_pooled);
    cudaGetSymbolAddress((void**)&counts, g_counts);

    // degree -> dinv
    deg_init<<<(n + 255) / 256, 256>>>(dinv, n);
    deg_count<<<(E + 255) / 256, 256>>>(dst, dinv, E);
    deg_rsqrt<<<(n + 255) / 256, 256>>>(dinv, n);

    const int n4 = n * 32;                       // float4 count per feature map
    const float* hin = x;
    for (int l = 0; l < 4; l++) {
        gemm_nn<<<(n + 127) / 128, 256>>>(hin, W[l], buf1, n);
        selfloop_bias<<<(n4 + 255) / 256, 256>>>(buf1, dinv, bv[l], buf2, n);
        scatter_edges<<<(E + 7) / 8, 256>>>(buf1, src, dst, dinv, buf2, E);
        relu_k<<<(n4 + 255) / 256, 256>>>(buf2, buf0, n4);
        hin = buf0;
    }

    zero_pool<<<(G * HD + 255) / 256, 256>>>(pooled, counts, G);
    pool_nodes<<<(n + 7) / 8, 256>>>(buf0, batch, pooled, counts, n);
    final_linear<<<G, 128>>>(pooled, counts, linW, linb, out);
}

// round 2
// speedup vs baseline: 1.9168x; 1.9168x over previous
#include <cuda_runtime.h>
#include <cstddef>

#define HD   128
#define NMAX 100000
#define GMAX 1024
#define EMAX 1700000
#define ELLW 64

// ---------------- scratch (device globals; no allocation allowed) ----------
__device__ __align__(256) float g_buf0[NMAX * HD];    // h (layer output)
__device__ __align__(256) float g_buf1[NMAX * HD];    // m' = (h @ W) * dinv[row]
__device__ __align__(256) int   g_ell[NMAX * ELLW];   // ELL adjacency: dst -> srcs
__device__ __align__(256) int   g_cnt[NMAX];          // in-degree (excl self)
__device__ __align__(256) float g_dinv[NMAX];
__device__ __align__(256) float g_pooled[GMAX * HD];
__device__ __align__(256) float g_counts[GMAX];

// ---------------- graph build ----------------------------------------------
__global__ void zero_cnt(int* __restrict__ cnt, int n) {
    int i = blockIdx.x * blockDim.x + threadIdx.x;
    if (i < n) cnt[i] = 0;
}

__global__ void fill_ell(const int* __restrict__ src, const int* __restrict__ dst,
                         int* __restrict__ cnt, int* __restrict__ ell, int E)
{
    int e = blockIdx.x * blockDim.x + threadIdx.x;
    if (e >= E) return;
    int d = dst[e];
    int pos = atomicAdd(&cnt[d], 1);
    if (pos < ELLW) ell[(size_t)d * ELLW + pos] = src[e];
}

__global__ void make_dinv(const int* __restrict__ cnt, float* __restrict__ dinv, int n) {
    int i = blockIdx.x * blockDim.x + threadIdx.x;
    if (i < n) dinv[i] = rsqrtf((float)cnt[i] + 1.0f);   // +1 self-loop
}

// ---------------- GEMM: C[r,:] = (A[r,:] @ B) * dinv[r] --------------------
// 128x128 tile, BK=32, 256 threads, 8x8 microtile, packed fma.rn.f32x2.
__device__ __forceinline__ unsigned long long dup_f32(float a) {
    unsigned long long p;
    asm("mov.b64 %0, {%1, %1};" : "=l"(p) : "r"(__float_as_uint(a)));
    return p;
}
__device__ __forceinline__ void ffma2(unsigned long long& d,
                                      unsigned long long a, unsigned long long b) {
    asm("fma.rn.f32x2 %0, %1, %2, %3;" : "=l"(d) : "l"(a), "l"(b), "l"(d));
}
__device__ __forceinline__ float2 unpack2(unsigned long long v) {
    float2 r;
    asm("mov.b64 {%0, %1}, %2;" : "=f"(r.x), "=f"(r.y) : "l"(v));
    return r;
}

__global__ __launch_bounds__(256) void gemm_scaled(
    const float* __restrict__ A, const float* __restrict__ B,
    const float* __restrict__ dinv, float* __restrict__ C, int n)
{
    __shared__ float As[32][128];   // [k][m]
    __shared__ float Bs[32][128];   // [k][n]

    const int tid = threadIdx.x;
    const int tx  = tid & 15;
    const int ty  = tid >> 4;
    const int row0 = blockIdx.x * 128;

    unsigned long long acc[8][4];
#pragma unroll
    for (int i = 0; i < 8; i++)
#pragma unroll
        for (int j = 0; j < 4; j++) acc[i][j] = 0ull;

    for (int k0 = 0; k0 < 128; k0 += 32) {
#pragma unroll
        for (int l = 0; l < 4; l++) {
            int idx = tid + l * 256;
            int r = idx >> 3;
            int c = (idx & 7) << 2;
            int gr = row0 + r;
            float4 v = make_float4(0.f, 0.f, 0.f, 0.f);
            if (gr < n) v = *(const float4*)(A + (size_t)gr * HD + k0 + c);
            As[c + 0][r] = v.x; As[c + 1][r] = v.y;
            As[c + 2][r] = v.z; As[c + 3][r] = v.w;
            int r2 = idx >> 5;
            int c2 = (idx & 31) << 2;
            *(float4*)&Bs[r2][c2] = *(const float4*)(B + (size_t)(k0 + r2) * HD + c2);
        }
        __syncthreads();

#pragma unroll
        for (int k = 0; k < 32; k++) {
            float a[8];
            *(float4*)&a[0] = *(const float4*)&As[k][ty * 8];
            *(float4*)&a[4] = *(const float4*)&As[k][ty * 8 + 4];
            unsigned long long b2[4];
            *(ulonglong2*)&b2[0] = *(const ulonglong2*)&Bs[k][tx * 8];
            *(ulonglong2*)&b2[2] = *(const ulonglong2*)&Bs[k][tx * 8 + 4];
#pragma unroll
            for (int i = 0; i < 8; i++) {
                unsigned long long ad = dup_f32(a[i]);
#pragma unroll
                for (int j = 0; j < 4; j++) ffma2(acc[i][j], ad, b2[j]);
            }
        }
        __syncthreads();
    }

#pragma unroll
    for (int i = 0; i < 8; i++) {
        int gr = row0 + ty * 8 + i;
        if (gr < n) {
            float w = dinv[gr];
            float2 p0 = unpack2(acc[i][0]);
            float2 p1 = unpack2(acc[i][1]);
            float2 p2 = unpack2(acc[i][2]);
            float2 p3 = unpack2(acc[i][3]);
            float4 v0 = make_float4(p0.x * w, p0.y * w, p1.x * w, p1.y * w);
            float4 v1 = make_float4(p2.x * w, p2.y * w, p3.x * w, p3.y * w);
            *(float4*)(C + (size_t)gr * HD + tx * 8)     = v0;
            *(float4*)(C + (size_t)gr * HD + tx * 8 + 4) = v1;
        }
    }
}

// ---------------- fused gather + selfloop + bias + relu ---------------------
// one warp per dst node: h[d] = relu( dinv[d] * (m'[d] + sum_e m'[src_e]) + b )
__global__ __launch_bounds__(256) void gather_nodes(
    const float* __restrict__ m, const int* __restrict__ ell,
    const int* __restrict__ cnt, const float* __restrict__ dinv,
    const float* __restrict__ bias, float* __restrict__ h, int n)
{
    int d = blockIdx.x * (blockDim.x >> 5) + (threadIdx.x >> 5);
    if (d >= n) return;
    const int lane = threadIdx.x & 31;
    const int c4 = lane << 2;

    float4 acc = *(const float4*)(m + (size_t)d * HD + c4);   // self term
    const int deg = cnt[d];
    const int* row = ell + (size_t)d * ELLW;

    for (int base = 0; base < deg; base += 32) {
        int idx = (base + lane < deg) ? __ldg(row + base + lane) : 0;
        int lim = min(32, deg - base);
#pragma unroll 4
        for (int j = 0; j < lim; j++) {
            int s = __shfl_sync(0xffffffffu, idx, j);
            float4 v = *(const float4*)(m + (size_t)s * HD + c4);
            acc.x += v.x; acc.y += v.y; acc.z += v.z; acc.w += v.w;
        }
    }

    float w = dinv[d];
    float4 bb = *(const float4*)(bias + c4);
    float4 o;
    o.x = fmaxf(fmaf(acc.x, w, bb.x), 0.f);
    o.y = fmaxf(fmaf(acc.y, w, bb.y), 0.f);
    o.z = fmaxf(fmaf(acc.z, w, bb.z), 0.f);
    o.w = fmaxf(fmaf(acc.w, w, bb.w), 0.f);
    *(float4*)(h + (size_t)d * HD + c4) = o;
}

// ---------------- pooling ----------------------------------------------------
__global__ void zero_pool(float* __restrict__ pooled, float* __restrict__ counts, int G) {
    int i = blockIdx.x * blockDim.x + threadIdx.x;
    if (i < G * HD) pooled[i] = 0.0f;
    if (i < G) counts[i] = 0.0f;
}

__global__ void pool_nodes(const float* __restrict__ h, const int* __restrict__ batch,
                           float* __restrict__ pooled, float* __restrict__ counts, int n)
{
    int i = blockIdx.x * (blockDim.x >> 5) + (threadIdx.x >> 5);
    if (i >= n) return;
    int lane = threadIdx.x & 31;
    int g = batch[i];
    float4 v = *(const float4*)(h + (size_t)i * HD + (lane << 2));
    float* p = pooled + (size_t)g * HD + (lane << 2);
    asm volatile("red.global.add.v4.f32 [%0], {%1, %2, %3, %4};"
                 :: "l"(p), "f"(v.x), "f"(v.y), "f"(v.z), "f"(v.w)
                 : "memory");
    if (lane == 0) atomicAdd(&counts[g], 1.0f);
}

// ---------------- final linear head ------------------------------------------
__global__ void final_linear(const float* __restrict__ pooled, const float* __restrict__ counts,
                             const float* __restrict__ linW, const float* __restrict__ linb,
                             float* __restrict__ out)
{
    int g = blockIdx.x;
    int c = threadIdx.x;          // 128 threads
    float cntv = fmaxf(counts[g], 1.0f);
    float p = pooled[g * HD + c] / cntv;
    float v0 = p * linW[c * 2 + 0];
    float v1 = p * linW[c * 2 + 1];
#pragma unroll
    for (int o = 16; o > 0; o >>= 1) {
        v0 += __shfl_xor_sync(0xffffffffu, v0, o);
        v1 += __shfl_xor_sync(0xffffffffu, v1, o);
    }
    __shared__ float s0[4], s1[4];
    int w = threadIdx.x >> 5;
    if ((threadIdx.x & 31) == 0) { s0[w] = v0; s1[w] = v1; }
    __syncthreads();
    if (threadIdx.x == 0) {
        out[g * 2 + 0] = s0[0] + s0[1] + s0[2] + s0[3] + linb[0];
        out[g * 2 + 1] = s1[0] + s1[1] + s1[2] + s1[3] + linb[1];
    }
}

// ---------------- launch -------------------------------------------------------
extern "C" void kernel_launch(void* const* d_in, const int* in_sizes, int n_in,
                              void* d_out, int out_size)
{
    const float* x     = (const float*)d_in[0];
    const int*   ei    = (const int*)d_in[1];
    const int*   batch = (const int*)d_in[2];
    const float* W[4]  = {(const float*)d_in[3], (const float*)d_in[5],
                          (const float*)d_in[7], (const float*)d_in[9]};
    const float* bv[4] = {(const float*)d_in[4], (const float*)d_in[6],
                          (const float*)d_in[8], (const float*)d_in[10]};
    const float* linW  = (const float*)d_in[11];
    const float* linb  = (const float*)d_in[12];
    float* out = (float*)d_out;

    const int n = in_sizes[0] / HD;
    const int E = in_sizes[1] / 2;
    const int G = out_size / 2;
    const int* src = ei;
    const int* dst = ei + E;

    float *buf0, *buf1, *dinv, *pooled, *counts;
    int *ell, *cnt;
    cudaGetSymbolAddress((void**)&buf0,   g_buf0);
    cudaGetSymbolAddress((void**)&buf1,   g_buf1);
    cudaGetSymbolAddress((void**)&ell,    g_ell);
    cudaGetSymbolAddress((void**)&cnt,    g_cnt);
    cudaGetSymbolAddress((void**)&dinv,   g_dinv);
    cudaGetSymbolAddress((void**)&pooled, g_pooled);
    cudaGetSymbolAddress((void**)&counts, g_counts);

    // build ELL adjacency + dinv
    zero_cnt<<<(n + 255) / 256, 256>>>(cnt, n);
    fill_ell<<<(E + 255) / 256, 256>>>(src, dst, cnt, ell, E);
    make_dinv<<<(n + 255) / 256, 256>>>(cnt, dinv, n);

    const float* hin = x;
    for (int l = 0; l < 4; l++) {
        gemm_scaled<<<(n + 127) / 128, 256>>>(hin, W[l], dinv, buf1, n);
        gather_nodes<<<(n + 7) / 8, 256>>>(buf1, ell, cnt, dinv, bv[l], buf0, n);
        hin = buf0;
    }

    zero_pool<<<(G * HD + 255) / 256, 256>>>(pooled, counts, G);
    pool_nodes<<<(n + 7) / 8, 256>>>(buf0, batch, pooled, counts, n);
    final_linear<<<G, 128>>>(pooled, counts, linW, linb, out);
}

// round 4
// speedup vs baseline: 2.6609x; 1.3882x over previous
#include <cuda_runtime.h>
#include <cuda_bf16.h>
#include <cstdint>
#include <cstddef>

#define HD   128
#define NMAX 100000
#define GMAX 1024
#define ELLW 64

// ---------------- scratch (device globals; no allocation allowed) ----------
__device__ __align__(256) float g_buf0[NMAX * HD];            // h f32 (last layer)
__device__ __align__(256) float g_buf1[NMAX * HD];            // m' = (h @ W) * dinv[row]
__device__ __align__(256) __nv_bfloat16 g_hi[NMAX * HD];      // h split hi
__device__ __align__(256) __nv_bfloat16 g_lo[NMAX * HD];      // h split lo
__device__ __align__(256) __nv_bfloat16 g_whi[4 * HD * HD];   // W^T split hi ([N,K] row-major)
__device__ __align__(256) __nv_bfloat16 g_wlo[4 * HD * HD];   // W^T split lo
__device__ __align__(256) int   g_ell[NMAX * ELLW];
__device__ __align__(256) int   g_cnt[NMAX];
__device__ __align__(256) float g_dinv[NMAX];
__device__ __align__(256) float g_pooled[GMAX * HD];
__device__ __align__(256) float g_counts[GMAX];

// ---------------- helpers ----------------------------------------------------
__device__ __forceinline__ uint32_t smem_u32(const void* p) {
    uint32_t a;
    asm("{ .reg .u64 t; cvta.to.shared.u64 t, %1; cvt.u32.u64 %0, t; }" : "=r"(a) : "l"(p));
    return a;
}

__device__ __forceinline__ void ldm4(uint32_t* r, uint32_t addr) {
    asm volatile("ldmatrix.sync.aligned.m8n8.x4.shared.b16 {%0,%1,%2,%3}, [%4];"
                 : "=r"(r[0]), "=r"(r[1]), "=r"(r[2]), "=r"(r[3]) : "r"(addr));
}

__device__ __forceinline__ void mma_bf16(float* c, const uint32_t* a,
                                         uint32_t b0, uint32_t b1) {
    asm volatile(
        "mma.sync.aligned.m16n8k16.row.col.f32.bf16.bf16.f32 "
        "{%0,%1,%2,%3}, {%4,%5,%6,%7}, {%8,%9}, {%0,%1,%2,%3};"
        : "+f"(c[0]), "+f"(c[1]), "+f"(c[2]), "+f"(c[3])
        : "r"(a[0]), "r"(a[1]), "r"(a[2]), "r"(a[3]), "r"(b0), "r"(b1));
}

// SMEM plan: padded rows, stride 136 bf16 = 272 bytes (conflict-free ldmatrix)
#define ROWB 272
#define SA_HI 0
#define SA_LO (SA_HI + 64 * ROWB)
#define SW_HI (SA_LO + 64 * ROWB)
#define SW_LO (SW_HI + 128 * ROWB)
#define S_TOT (SW_LO + 128 * ROWB)

// ---------------- HMMA GEMM: C[r,:] = (A[r,:] @ W) * dinv[r] ----------------
// A as bf16 hi/lo [n,128]; W^T as bf16 hi/lo [128,128] ([N,K] row-major).
// block tile: 64m x 128n, 8 warps = 4 m-strips x 2 n-halves, full K=128.
__global__ __launch_bounds__(256, 2) void gemm_hmma(
    const __nv_bfloat16* __restrict__ Ahi, const __nv_bfloat16* __restrict__ Alo,
    const __nv_bfloat16* __restrict__ Whi, const __nv_bfloat16* __restrict__ Wlo,
    const float* __restrict__ dinv, float* __restrict__ C, int n)
{
    extern __shared__ char smem[];
    const uint32_t sb = smem_u32(smem);
    const int tid = threadIdx.x;
    const int row0 = blockIdx.x * 64;

    // ---- load tiles ----
    const uint4 z4 = make_uint4(0, 0, 0, 0);
#pragma unroll
    for (int i = 0; i < 4; i++) {                    // A: 64 rows x 16 uint4
        int idx = tid + i * 256;
        int r = idx >> 4, c = idx & 15;
        int gr = row0 + r;
        uint4 vh = z4, vl = z4;
        if (gr < n) {
            vh = *(const uint4*)(Ahi + (size_t)gr * HD + c * 8);
            vl = *(const uint4*)(Alo + (size_t)gr * HD + c * 8);
        }
        *(uint4*)(smem + SA_HI + r * ROWB + c * 16) = vh;
        *(uint4*)(smem + SA_LO + r * ROWB + c * 16) = vl;
    }
#pragma unroll
    for (int i = 0; i < 8; i++) {                    // W: 128 rows x 16 uint4
        int idx = tid + i * 256;
        int r = idx >> 4, c = idx & 15;
        *(uint4*)(smem + SW_HI + r * ROWB + c * 16) =
            *(const uint4*)(Whi + (size_t)r * HD + c * 8);
        *(uint4*)(smem + SW_LO + r * ROWB + c * 16) =
            *(const uint4*)(Wlo + (size_t)r * HD + c * 8);
    }
    __syncthreads();

    // ---- compute ----
    const int wid = tid >> 5, lane = tid & 31;
    const int mstrip = wid & 3;        // 0..3 -> m rows mstrip*16
    const int nhalf  = wid >> 2;       // 0..1 -> n cols nhalf*64
    const int lrow = lane & 15, lcol = lane >> 4;

    float acc[8][4];
#pragma unroll
    for (int p = 0; p < 8; p++)
#pragma unroll
        for (int j = 0; j < 4; j++) acc[p][j] = 0.0f;

    const uint32_t a_hi0 = sb + SA_HI + (mstrip * 16 + lrow) * ROWB + lcol * 16;
    const uint32_t a_lo0 = sb + SA_LO + (mstrip * 16 + lrow) * ROWB + lcol * 16;
    const uint32_t w_hi0 = sb + SW_HI + (nhalf * 64 + lrow) * ROWB + lcol * 16;
    const uint32_t w_lo0 = sb + SW_LO + (nhalf * 64 + lrow) * ROWB + lcol * 16;

#pragma unroll
    for (int ks = 0; ks < 8; ks++) {
        uint32_t ah[4], al[4];
        ldm4(ah, a_hi0 + ks * 32);
        ldm4(al, a_lo0 + ks * 32);
#pragma unroll
        for (int p = 0; p < 4; p++) {                // n16 per iteration
            uint32_t wh[4], wl[4];
            ldm4(wh, w_hi0 + p * (16 * ROWB) + ks * 32);
            mma_bf16(acc[2 * p],     ah, wh[0], wh[2]);
            mma_bf16(acc[2 * p + 1], ah, wh[1], wh[3]);
            mma_bf16(acc[2 * p],     al, wh[0], wh[2]);
            mma_bf16(acc[2 * p + 1], al, wh[1], wh[3]);
            ldm4(wl, w_lo0 + p * (16 * ROWB) + ks * 32);
            mma_bf16(acc[2 * p],     ah, wl[0], wl[2]);
            mma_bf16(acc[2 * p + 1], ah, wl[1], wl[3]);
        }
    }

    // ---- epilogue: scale by dinv[row], store ----
    const int rbase = row0 + mstrip * 16 + (lane >> 2);
    const int qc = (lane & 3) * 2;
#pragma unroll
    for (int rr = 0; rr < 2; rr++) {
        int row = rbase + rr * 8;
        if (row < n) {
            float w = dinv[row];
            float* dst = C + (size_t)row * HD + nhalf * 64 + qc;
#pragma unroll
            for (int p = 0; p < 8; p++) {
                float2 v = make_float2(acc[p][rr * 2] * w, acc[p][rr * 2 + 1] * w);
                *(float2*)(dst + p * 8) = v;
            }
        }
    }
}

// ---------------- graph build ------------------------------------------------
__global__ void zero_cnt(int* __restrict__ cnt, int n) {
    int i = blockIdx.x * blockDim.x + threadIdx.x;
    if (i < n) cnt[i] = 0;
}

__global__ void fill_ell(const int* __restrict__ src, const int* __restrict__ dst,
                         int* __restrict__ cnt, int* __restrict__ ell, int E)
{
    int e = blockIdx.x * blockDim.x + threadIdx.x;
    if (e >= E) return;
    int d = dst[e];
    int pos = atomicAdd(&cnt[d], 1);
    if (pos < ELLW) ell[(size_t)d * ELLW + pos] = src[e];
}

__global__ void make_dinv(const int* __restrict__ cnt, float* __restrict__ dinv, int n) {
    int i = blockIdx.x * blockDim.x + threadIdx.x;
    if (i < n) dinv[i] = rsqrtf((float)cnt[i] + 1.0f);
}

// ---------------- weight split + transpose: Wsp[n,k] = split(W[k,n]) --------
__global__ void wsplit(const float* __restrict__ W, __nv_bfloat16* __restrict__ Bhi,
                       __nv_bfloat16* __restrict__ Blo)
{
    int idx = blockIdx.x * blockDim.x + threadIdx.x;
    if (idx >= HD * HD) return;
    int nn = idx >> 7, kk = idx & 127;
    float v = W[kk * HD + nn];
    __nv_bfloat16 hi = __float2bfloat16(v);
    __nv_bfloat16 lo = __float2bfloat16(v - __bfloat162float(hi));
    Bhi[idx] = hi;
    Blo[idx] = lo;
}

// ---------------- input split ------------------------------------------------
__global__ void xsplit(const float* __restrict__ x, __nv_bfloat16* __restrict__ hi,
                       __nv_bfloat16* __restrict__ lo, int total)
{
    int i = blockIdx.x * blockDim.x + threadIdx.x;
    if (i >= total) return;
    float v = x[i];
    __nv_bfloat16 h = __float2bfloat16(v);
    hi[i] = h;
    lo[i] = __float2bfloat16(v - __bfloat162float(h));
}

// ---------------- fused gather + selfloop + bias + relu (+ hi/lo split) -----
__global__ __launch_bounds__(256) void gather_nodes(
    const float* __restrict__ m, const int* __restrict__ ell,
    const int* __restrict__ cnt, const float* __restrict__ dinv,
    const float* __restrict__ bias,
    __nv_bfloat16* __restrict__ out_hi, __nv_bfloat16* __restrict__ out_lo,
    float* __restrict__ out_f32, int mode, int n)
{
    int d = blockIdx.x * (blockDim.x >> 5) + (threadIdx.x >> 5);
    if (d >= n) return;
    const int lane = threadIdx.x & 31;
    const int c4 = lane << 2;

    float4 acc = *(const float4*)(m + (size_t)d * HD + c4);   // self term
    const int deg = cnt[d];
    const int* row = ell + (size_t)d * ELLW;

    for (int base = 0; base < deg; base += 32) {
        int idx = (base + lane < deg) ? __ldg(row + base + lane) : 0;
        int lim = min(32, deg - base);
#pragma unroll 4
        for (int j = 0; j < lim; j++) {
            int s = __shfl_sync(0xffffffffu, idx, j);
            float4 v = *(const float4*)(m + (size_t)s * HD + c4);
            acc.x += v.x; acc.y += v.y; acc.z += v.z; acc.w += v.w;
        }
    }

    float w = dinv[d];
    float4 bb = *(const float4*)(bias + c4);
    float o0 = fmaxf(fmaf(acc.x, w, bb.x), 0.f);
    float o1 = fmaxf(fmaf(acc.y, w, bb.y), 0.f);
    float o2 = fmaxf(fmaf(acc.z, w, bb.z), 0.f);
    float o3 = fmaxf(fmaf(acc.w, w, bb.w), 0.f);

    if (mode == 0) {
        __nv_bfloat16 h0 = __float2bfloat16(o0), h1 = __float2bfloat16(o1);
        __nv_bfloat16 h2 = __float2bfloat16(o2), h3 = __float2bfloat16(o3);
        __nv_bfloat162 hv0 = {h0, h1}, hv1 = {h2, h3};
        __nv_bfloat162 lv0 = {__float2bfloat16(o0 - __bfloat162float(h0)),
                              __float2bfloat16(o1 - __bfloat162float(h1))};
        __nv_bfloat162 lv1 = {__float2bfloat16(o2 - __bfloat162float(h2)),
                              __float2bfloat16(o3 - __bfloat162float(h3))};
        *(__nv_bfloat162*)(out_hi + (size_t)d * HD + c4)     = hv0;
        *(__nv_bfloat162*)(out_hi + (size_t)d * HD + c4 + 2) = hv1;
        *(__nv_bfloat162*)(out_lo + (size_t)d * HD + c4)     = lv0;
        *(__nv_bfloat162*)(out_lo + (size_t)d * HD + c4 + 2) = lv1;
    } else {
        *(float4*)(out_f32 + (size_t)d * HD + c4) = make_float4(o0, o1, o2, o3);
    }
}

// ---------------- pooling ------------------------------------------------------
__global__ void zero_pool(float* __restrict__ pooled, float* __restrict__ counts, int G) {
    int i = blockIdx.x * blockDim.x + threadIdx.x;
    if (i < G * HD) pooled[i] = 0.0f;
    if (i < G) counts[i] = 0.0f;
}

__global__ void pool_nodes(const float* __restrict__ h, const int* __restrict__ batch,
                           float* __restrict__ pooled, float* __restrict__ counts, int n)
{
    int i = blockIdx.x * (blockDim.x >> 5) + (threadIdx.x >> 5);
    if (i >= n) return;
    int lane = threadIdx.x & 31;
    int g = batch[i];
    float4 v = *(const float4*)(h + (size_t)i * HD + (lane << 2));
    float* p = pooled + (size_t)g * HD + (lane << 2);
    asm volatile("red.global.add.v4.f32 [%0], {%1, %2, %3, %4};"
                 :: "l"(p), "f"(v.x), "f"(v.y), "f"(v.z), "f"(v.w) : "memory");
    if (lane == 0) atomicAdd(&counts[g], 1.0f);
}

// ---------------- final linear head --------------------------------------------
__global__ void final_linear(const float* __restrict__ pooled, const float* __restrict__ counts,
                             const float* __restrict__ linW, const float* __restrict__ linb,
                             float* __restrict__ out)
{
    int g = blockIdx.x;
    int c = threadIdx.x;
    float cntv = fmaxf(counts[g], 1.0f);
    float p = pooled[g * HD + c] / cntv;
    float v0 = p * linW[c * 2 + 0];
    float v1 = p * linW[c * 2 + 1];
#pragma unroll
    for (int o = 16; o > 0; o >>= 1) {
        v0 += __shfl_xor_sync(0xffffffffu, v0, o);
        v1 += __shfl_xor_sync(0xffffffffu, v1, o);
    }
    __shared__ float s0[4], s1[4];
    int w = threadIdx.x >> 5;
    if ((threadIdx.x & 31) == 0) { s0[w] = v0; s1[w] = v1; }
    __syncthreads();
    if (threadIdx.x == 0) {
        out[g * 2 + 0] = s0[0] + s0[1] + s0[2] + s0[3] + linb[0];
        out[g * 2 + 1] = s1[0] + s1[1] + s1[2] + s1[3] + linb[1];
    }
}

// ---------------- launch ---------------------------------------------------------
extern "C" void kernel_launch(void* const* d_in, const int* in_sizes, int n_in,
                              void* d_out, int out_size)
{
    const float* x     = (const float*)d_in[0];
    const int*   ei    = (const int*)d_in[1];
    const int*   batch = (const int*)d_in[2];
    const float* W[4]  = {(const float*)d_in[3], (const float*)d_in[5],
                          (const float*)d_in[7], (const float*)d_in[9]};
    const float* bv[4] = {(const float*)d_in[4], (const float*)d_in[6],
                          (const float*)d_in[8], (const float*)d_in[10]};
    const float* linW  = (const float*)d_in[11];
    const float* linb  = (const float*)d_in[12];
    float* out = (float*)d_out;

    const int n = in_sizes[0] / HD;
    const int E = in_sizes[1] / 2;
    const int G = out_size / 2;
    const int* src = ei;
    const int* dst = ei + E;

    float *buf0, *buf1, *dinv, *pooled, *counts;
    int *ell, *cnt;
    __nv_bfloat16 *hi, *lo, *whi, *wlo;
    cudaGetSymbolAddress((void**)&buf0,   g_buf0);
    cudaGetSymbolAddress((void**)&buf1,   g_buf1);
    cudaGetSymbolAddress((void**)&hi,     g_hi);
    cudaGetSymbolAddress((void**)&lo,     g_lo);
    cudaGetSymbolAddress((void**)&whi,    g_whi);
    cudaGetSymbolAddress((void**)&wlo,    g_wlo);
    cudaGetSymbolAddress((void**)&ell,    g_ell);
    cudaGetSymbolAddress((void**)&cnt,    g_cnt);
    cudaGetSymbolAddress((void**)&dinv,   g_dinv);
    cudaGetSymbolAddress((void**)&pooled, g_pooled);
    cudaGetSymbolAddress((void**)&counts, g_counts);

    cudaFuncSetAttribute(gemm_hmma, cudaFuncAttributeMaxDynamicSharedMemorySize, S_TOT);

    // graph build + weight/input splits
    zero_cnt<<<(n + 255) / 256, 256>>>(cnt, n);
    fill_ell<<<(E + 255) / 256, 256>>>(src, dst, cnt, ell, E);
    make_dinv<<<(n + 255) / 256, 256>>>(cnt, dinv, n);
    for (int l = 0; l < 4; l++)
        wsplit<<<(HD * HD + 255) / 256, 256>>>(W[l], whi + l * HD * HD, wlo + l * HD * HD);
    xsplit<<<(n * HD + 255) / 256, 256>>>(x, hi, lo, n * HD);

    const int tiles = (n + 63) / 64;
    for (int l = 0; l < 4; l++) {
        gemm_hmma<<<tiles, 256, S_TOT>>>(hi, lo, whi + l * HD * HD, wlo + l * HD * HD,
                                         dinv, buf1, n);
        gather_nodes<<<(n + 7) / 8, 256>>>(buf1, ell, cnt, dinv, bv[l],
                                           hi, lo, buf0, (l == 3) ? 1 : 0, n);
    }

    zero_pool<<<(G * HD + 255) / 256, 256>>>(pooled, counts, G);
    pool_nodes<<<(n + 7) / 8, 256>>>(buf0, batch, pooled, counts, n);
    final_linear<<<G, 128>>>(pooled, counts, linW, linb, out);
}

// round 5
// speedup vs baseline: 2.9831x; 1.1211x over previous
#include <cuda_runtime.h>
#include <cuda_bf16.h>
#include <cuda_fp16.h>
#include <cstdint>
#include <cstddef>

#define HD   128
#define NMAX 100000
#define GMAX 1024
#define ELLW 64

// ---------------- scratch (device globals; no allocation allowed) ----------
__device__ __align__(256) float  g_buf0[NMAX * HD];           // h f32 (last layer)
__device__ __align__(256) __half g_msg[NMAX * HD];            // m' fp16 = (h @ W) * dinv[row]
__device__ __align__(256) __nv_bfloat16 g_hi[NMAX * HD];      // h split hi
__device__ __align__(256) __nv_bfloat16 g_lo[NMAX * HD];      // h split lo
__device__ __align__(256) __nv_bfloat16 g_whi[4 * HD * HD];   // W^T split hi ([N,K] row-major)
__device__ __align__(256) __nv_bfloat16 g_wlo[4 * HD * HD];   // W^T split lo
__device__ __align__(256) int   g_ell[NMAX * ELLW];
__device__ __align__(256) int   g_cnt[NMAX];
__device__ __align__(256) float g_dinv[NMAX];
__device__ __align__(256) float g_pooled[GMAX * HD];
__device__ __align__(256) float g_counts[GMAX];

// ---------------- helpers ----------------------------------------------------
__device__ __forceinline__ uint32_t smem_u32(const void* p) {
    uint32_t a;
    asm("{ .reg .u64 t; cvta.to.shared.u64 t, %1; cvt.u32.u64 %0, t; }" : "=r"(a) : "l"(p));
    return a;
}

__device__ __forceinline__ void ldm4(uint32_t* r, uint32_t addr) {
    asm volatile("ldmatrix.sync.aligned.m8n8.x4.shared.b16 {%0,%1,%2,%3}, [%4];"
                 : "=r"(r[0]), "=r"(r[1]), "=r"(r[2]), "=r"(r[3]) : "r"(addr));
}

__device__ __forceinline__ void mma_bf16(float* c, const uint32_t* a,
                                         uint32_t b0, uint32_t b1) {
    asm volatile(
        "mma.sync.aligned.m16n8k16.row.col.f32.bf16.bf16.f32 "
        "{%0,%1,%2,%3}, {%4,%5,%6,%7}, {%8,%9}, {%0,%1,%2,%3};"
        : "+f"(c[0]), "+f"(c[1]), "+f"(c[2]), "+f"(c[3])
        : "r"(a[0]), "r"(a[1]), "r"(a[2]), "r"(a[3]), "r"(b0), "r"(b1));
}

// SMEM plan: padded rows, stride 136 bf16 = 272 bytes (conflict-free ldmatrix)
#define ROWB 272
#define SA_HI 0
#define SA_LO (SA_HI + 64 * ROWB)
#define SW_HI (SA_LO + 64 * ROWB)
#define SW_LO (SW_HI + 128 * ROWB)
#define S_TOT (SW_LO + 128 * ROWB)

// ---------------- HMMA GEMM: M[r,:] = fp16( (A[r,:] @ W) * dinv[r] ) --------
// A as bf16 hi/lo [n,128]; W^T as bf16 hi/lo [128,128] ([N,K] row-major).
// block tile: 64m x 128n, 8 warps = 4 m-strips x 2 n-halves, full K=128.
__global__ __launch_bounds__(256, 2) void gemm_hmma(
    const __nv_bfloat16* __restrict__ Ahi, const __nv_bfloat16* __restrict__ Alo,
    const __nv_bfloat16* __restrict__ Whi, const __nv_bfloat16* __restrict__ Wlo,
    const float* __restrict__ dinv, __half* __restrict__ M, int n)
{
    extern __shared__ char smem[];
    const uint32_t sb = smem_u32(smem);
    const int tid = threadIdx.x;
    const int row0 = blockIdx.x * 64;

    // ---- load tiles ----
    const uint4 z4 = make_uint4(0, 0, 0, 0);
#pragma unroll
    for (int i = 0; i < 4; i++) {                    // A: 64 rows x 16 uint4
        int idx = tid + i * 256;
        int r = idx >> 4, c = idx & 15;
        int gr = row0 + r;
        uint4 vh = z4, vl = z4;
        if (gr < n) {
            vh = *(const uint4*)(Ahi + (size_t)gr * HD + c * 8);
            vl = *(const uint4*)(Alo + (size_t)gr * HD + c * 8);
        }
        *(uint4*)(smem + SA_HI + r * ROWB + c * 16) = vh;
        *(uint4*)(smem + SA_LO + r * ROWB + c * 16) = vl;
    }
#pragma unroll
    for (int i = 0; i < 8; i++) {                    // W: 128 rows x 16 uint4
        int idx = tid + i * 256;
        int r = idx >> 4, c = idx & 15;
        *(uint4*)(smem + SW_HI + r * ROWB + c * 16) =
            *(const uint4*)(Whi + (size_t)r * HD + c * 8);
        *(uint4*)(smem + SW_LO + r * ROWB + c * 16) =
            *(const uint4*)(Wlo + (size_t)r * HD + c * 8);
    }
    __syncthreads();

    // ---- compute ----
    const int wid = tid >> 5, lane = tid & 31;
    const int mstrip = wid & 3;
    const int nhalf  = wid >> 2;
    const int lrow = lane & 15, lcol = lane >> 4;

    float acc[8][4];
#pragma unroll
    for (int p = 0; p < 8; p++)
#pragma unroll
        for (int j = 0; j < 4; j++) acc[p][j] = 0.0f;

    const uint32_t a_hi0 = sb + SA_HI + (mstrip * 16 + lrow) * ROWB + lcol * 16;
    const uint32_t a_lo0 = sb + SA_LO + (mstrip * 16 + lrow) * ROWB + lcol * 16;
    const uint32_t w_hi0 = sb + SW_HI + (nhalf * 64 + lrow) * ROWB + lcol * 16;
    const uint32_t w_lo0 = sb + SW_LO + (nhalf * 64 + lrow) * ROWB + lcol * 16;

#pragma unroll
    for (int ks = 0; ks < 8; ks++) {
        uint32_t ah[4], al[4];
        ldm4(ah, a_hi0 + ks * 32);
        ldm4(al, a_lo0 + ks * 32);
#pragma unroll
        for (int p = 0; p < 4; p++) {
            uint32_t wh[4], wl[4];
            ldm4(wh, w_hi0 + p * (16 * ROWB) + ks * 32);
            mma_bf16(acc[2 * p],     ah, wh[0], wh[2]);
            mma_bf16(acc[2 * p + 1], ah, wh[1], wh[3]);
            mma_bf16(acc[2 * p],     al, wh[0], wh[2]);
            mma_bf16(acc[2 * p + 1], al, wh[1], wh[3]);
            ldm4(wl, w_lo0 + p * (16 * ROWB) + ks * 32);
            mma_bf16(acc[2 * p],     ah, wl[0], wl[2]);
            mma_bf16(acc[2 * p + 1], ah, wl[1], wl[3]);
        }
    }

    // ---- epilogue: scale by dinv[row], store fp16 ----
    const int rbase = row0 + mstrip * 16 + (lane >> 2);
    const int qc = (lane & 3) * 2;
#pragma unroll
    for (int rr = 0; rr < 2; rr++) {
        int row = rbase + rr * 8;
        if (row < n) {
            float w = dinv[row];
            __half* dst = M + (size_t)row * HD + nhalf * 64 + qc;
#pragma unroll
            for (int p = 0; p < 8; p++) {
                __half2 v = __floats2half2_rn(acc[p][rr * 2] * w, acc[p][rr * 2 + 1] * w);
                *(__half2*)(dst + p * 8) = v;
            }
        }
    }
}

// ---------------- graph build ------------------------------------------------
__global__ void zero_cnt(int* __restrict__ cnt, int n) {
    int i = blockIdx.x * blockDim.x + threadIdx.x;
    if (i < n) cnt[i] = 0;
}

__global__ void fill_ell(const int* __restrict__ src, const int* __restrict__ dst,
                         int* __restrict__ cnt, int* __restrict__ ell, int E)
{
    int e = blockIdx.x * blockDim.x + threadIdx.x;
    if (e >= E) return;
    int d = dst[e];
    int pos = atomicAdd(&cnt[d], 1);
    if (pos < ELLW) ell[(size_t)d * ELLW + pos] = src[e];
}

__global__ void make_dinv(const int* __restrict__ cnt, float* __restrict__ dinv, int n) {
    int i = blockIdx.x * blockDim.x + threadIdx.x;
    if (i < n) dinv[i] = rsqrtf((float)cnt[i] + 1.0f);
}

// ---------------- weight split + transpose (all 4 layers in one launch) -----
__global__ void wsplit4(const float* __restrict__ W0, const float* __restrict__ W1,
                        const float* __restrict__ W2, const float* __restrict__ W3,
                        __nv_bfloat16* __restrict__ Bhi, __nv_bfloat16* __restrict__ Blo)
{
    int idx = blockIdx.x * blockDim.x + threadIdx.x;
    if (idx >= 4 * HD * HD) return;
    int l = idx >> 14;
    int r = idx & (HD * HD - 1);
    const float* W = (l == 0) ? W0 : (l == 1) ? W1 : (l == 2) ? W2 : W3;
    int nn = r >> 7, kk = r & 127;
    float v = W[kk * HD + nn];
    __nv_bfloat16 hi = __float2bfloat16(v);
    __nv_bfloat16 lo = __float2bfloat16(v - __bfloat162float(hi));
    Bhi[idx] = hi;
    Blo[idx] = lo;
}

// ---------------- input split ------------------------------------------------
__global__ void xsplit(const float* __restrict__ x, __nv_bfloat16* __restrict__ hi,
                       __nv_bfloat16* __restrict__ lo, int total)
{
    int i = blockIdx.x * blockDim.x + threadIdx.x;
    if (i >= total) return;
    float v = x[i];
    __nv_bfloat16 h = __float2bfloat16(v);
    hi[i] = h;
    lo[i] = __float2bfloat16(v - __bfloat162float(h));
}

// ---------------- fused gather + selfloop + bias + relu (+ hi/lo split) -----
// one warp per dst node, fp16 messages: lane covers 4 channels (8 bytes)
__global__ __launch_bounds__(256) void gather_nodes(
    const __half* __restrict__ m, const int* __restrict__ ell,
    const int* __restrict__ cnt, const float* __restrict__ dinv,
    const float* __restrict__ bias,
    __nv_bfloat16* __restrict__ out_hi, __nv_bfloat16* __restrict__ out_lo,
    float* __restrict__ out_f32, int mode, int n)
{
    int d = blockIdx.x * (blockDim.x >> 5) + (threadIdx.x >> 5);
    if (d >= n) return;
    const int lane = threadIdx.x & 31;
    const int c4 = lane << 2;

    // self term
    uint2 sraw = *(const uint2*)(m + (size_t)d * HD + c4);
    float2 s0 = __half22float2(*(const __half2*)&sraw.x);
    float2 s1 = __half22float2(*(const __half2*)&sraw.y);
    float a0 = s0.x, a1 = s0.y, a2 = s1.x, a3 = s1.y;

    const int deg = cnt[d];
    const int* row = ell + (size_t)d * ELLW;

    for (int base = 0; base < deg; base += 32) {
        int idx = (base + lane < deg) ? __ldg(row + base + lane) : 0;
        int lim = min(32, deg - base);
#pragma unroll 8
        for (int j = 0; j < lim; j++) {
            int s = __shfl_sync(0xffffffffu, idx, j);
            uint2 raw = *(const uint2*)(m + (size_t)s * HD + c4);
            float2 v0 = __half22float2(*(const __half2*)&raw.x);
            float2 v1 = __half22float2(*(const __half2*)&raw.y);
            a0 += v0.x; a1 += v0.y; a2 += v1.x; a3 += v1.y;
        }
    }

    float w = dinv[d];
    float4 bb = *(const float4*)(bias + c4);
    float o0 = fmaxf(fmaf(a0, w, bb.x), 0.f);
    float o1 = fmaxf(fmaf(a1, w, bb.y), 0.f);
    float o2 = fmaxf(fmaf(a2, w, bb.z), 0.f);
    float o3 = fmaxf(fmaf(a3, w, bb.w), 0.f);

    if (mode == 0) {
        __nv_bfloat16 h0 = __float2bfloat16(o0), h1 = __float2bfloat16(o1);
        __nv_bfloat16 h2 = __float2bfloat16(o2), h3 = __float2bfloat16(o3);
        __nv_bfloat162 hv0 = {h0, h1}, hv1 = {h2, h3};
        __nv_bfloat162 lv0 = {__float2bfloat16(o0 - __bfloat162float(h0)),
                              __float2bfloat16(o1 - __bfloat162float(h1))};
        __nv_bfloat162 lv1 = {__float2bfloat16(o2 - __bfloat162float(h2)),
                              __float2bfloat16(o3 - __bfloat162float(h3))};
        *(__nv_bfloat162*)(out_hi + (size_t)d * HD + c4)     = hv0;
        *(__nv_bfloat162*)(out_hi + (size_t)d * HD + c4 + 2) = hv1;
        *(__nv_bfloat162*)(out_lo + (size_t)d * HD + c4)     = lv0;
        *(__nv_bfloat162*)(out_lo + (size_t)d * HD + c4 + 2) = lv1;
    } else {
        *(float4*)(out_f32 + (size_t)d * HD + c4) = make_float4(o0, o1, o2, o3);
    }
}

// ---------------- pooling ------------------------------------------------------
__global__ void zero_pool(float* __restrict__ pooled, float* __restrict__ counts, int G) {
    int i = blockIdx.x * blockDim.x + threadIdx.x;
    if (i < G * HD) pooled[i] = 0.0f;
    if (i < G) counts[i] = 0.0f;
}

__global__ void pool_nodes(const float* __restrict__ h, const int* __restrict__ batch,
                           float* __restrict__ pooled, float* __restrict__ counts, int n)
{
    int i = blockIdx.x * (blockDim.x >> 5) + (threadIdx.x >> 5);
    if (i >= n) return;
    int lane = threadIdx.x & 31;
    int g = batch[i];
    float4 v = *(const float4*)(h + (size_t)i * HD + (lane << 2));
    float* p = pooled + (size_t)g * HD + (lane << 2);
    asm volatile("red.global.add.v4.f32 [%0], {%1, %2, %3, %4};"
                 :: "l"(p), "f"(v.x), "f"(v.y), "f"(v.z), "f"(v.w) : "memory");
    if (lane == 0) atomicAdd(&counts[g], 1.0f);
}

// ---------------- final linear head --------------------------------------------
__global__ void final_linear(const float* __restrict__ pooled, const float* __restrict__ counts,
                             const float* __restrict__ linW, const float* __restrict__ linb,
                             float* __restrict__ out)
{
    int g = blockIdx.x;
    int c = threadIdx.x;
    float cntv = fmaxf(counts[g], 1.0f);
    float p = pooled[g * HD + c] / cntv;
    float v0 = p * linW[c * 2 + 0];
    float v1 = p * linW[c * 2 + 1];
#pragma unroll
    for (int o = 16; o > 0; o >>= 1) {
        v0 += __shfl_xor_sync(0xffffffffu, v0, o);
        v1 += __shfl_xor_sync(0xffffffffu, v1, o);
    }
    __shared__ float s0[4], s1[4];
    int w = threadIdx.x >> 5;
    if ((threadIdx.x & 31) == 0) { s0[w] = v0; s1[w] = v1; }
    __syncthreads();
    if (threadIdx.x == 0) {
        out[g * 2 + 0] = s0[0] + s0[1] + s0[2] + s0[3] + linb[0];
        out[g * 2 + 1] = s1[0] + s1[1] + s1[2] + s1[3] + linb[1];
    }
}

// ---------------- launch ---------------------------------------------------------
extern "C" void kernel_launch(void* const* d_in, const int* in_sizes, int n_in,
                              void* d_out, int out_size)
{
    const float* x     = (const float*)d_in[0];
    const int*   ei    = (const int*)d_in[1];
    const int*   batch = (const int*)d_in[2];
    const float* W[4]  = {(const float*)d_in[3], (const float*)d_in[5],
                          (const float*)d_in[7], (const float*)d_in[9]};
    const float* bv[4] = {(const float*)d_in[4], (const float*)d_in[6],
                          (const float*)d_in[8], (const float*)d_in[10]};
    const float* linW  = (const float*)d_in[11];
    const float* linb  = (const float*)d_in[12];
    float* out = (float*)d_out;

    const int n = in_sizes[0] / HD;
    const int E = in_sizes[1] / 2;
    const int G = out_size / 2;
    const int* src = ei;
    const int* dst = ei + E;

    float *buf0, *dinv, *pooled, *counts;
    __half* msg;
    int *ell, *cnt;
    __nv_bfloat16 *hi, *lo, *whi, *wlo;
    cudaGetSymbolAddress((void**)&buf0,   g_buf0);
    cudaGetSymbolAddress((void**)&msg,    g_msg);
    cudaGetSymbolAddress((void**)&hi,     g_hi);
    cudaGetSymbolAddress((void**)&lo,     g_lo);
    cudaGetSymbolAddress((void**)&whi,    g_whi);
    cudaGetSymbolAddress((void**)&wlo,    g_wlo);
    cudaGetSymbolAddress((void**)&ell,    g_ell);
    cudaGetSymbolAddress((void**)&cnt,    g_cnt);
    cudaGetSymbolAddress((void**)&dinv,   g_dinv);
    cudaGetSymbolAddress((void**)&pooled, g_pooled);
    cudaGetSymbolAddress((void**)&counts, g_counts);

    cudaFuncSetAttribute(gemm_hmma, cudaFuncAttributeMaxDynamicSharedMemorySize, S_TOT);

    // graph build + weight/input splits
    zero_cnt<<<(n + 255) / 256, 256>>>(cnt, n);
    fill_ell<<<(E + 255) / 256, 256>>>(src, dst, cnt, ell, E);
    make_dinv<<<(n + 255) / 256, 256>>>(cnt, dinv, n);
    wsplit4<<<(4 * HD * HD + 255) / 256, 256>>>(W[0], W[1], W[2], W[3], whi, wlo);
    xsplit<<<(n * HD + 255) / 256, 256>>>(x, hi, lo, n * HD);

    const int tiles = (n + 63) / 64;
    for (int l = 0; l < 4; l++) {
        gemm_hmma<<<tiles, 256, S_TOT>>>(hi, lo, whi + l * HD * HD, wlo + l * HD * HD,
                                         dinv, msg, n);
        gather_nodes<<<(n + 7) / 8, 256>>>(msg, ell, cnt, dinv, bv[l],
                                           hi, lo, buf0, (l == 3) ? 1 : 0, n);
    }

    zero_pool<<<(G * HD + 255) / 256, 256>>>(pooled, counts, G);
    pool_nodes<<<(n + 7) / 8, 256>>>(buf0, batch, pooled, counts, n);
    final_linear<<<G, 128>>>(pooled, counts, linW, linb, out);
}